// round 1
// baseline (speedup 1.0000x reference)
#include <cuda_runtime.h>
#include <cuda_fp16.h>
#include <cstdint>

#define T_STEPS 2048
#define BATCH   128
#define DIM     100
#define HID     1024
#define NBLK    64
#define JT      16          // H columns per block
#define NTH     256
#define KC      128         // k-halfs per chunk
#define NCH     9           // 8 chunks of h + 1 chunk of x
#define XW      128         // padded x width (100 -> 128)
#define APITCH_B 272        // bytes per A-slab row (128 halfs + 8 pad)
#define WPITCH_H 1160       // halfs per W row (1152 + 8 pad)
#define WPITCH_B 2320
#define ABUF_B  (BATCH*APITCH_B)              // 34816 B per A buffer
#define SMEM_W_OFF   (2*ABUF_B)               // 69632
#define SMEM_BIAS_OFF (SMEM_W_OFF + JT*WPITCH_B)  // 106752
#define SMEM_TOTAL   (SMEM_BIAS_OFF + 64)

// ---------------- device scratch (no allocations allowed) ----------------
__device__ __half g_xT[(size_t)T_STEPS * BATCH * XW];  // x transposed+padded, fp16 (64 MB)
__device__ __half g_h[2][BATCH * HID];                 // double-buffered hidden state, fp16
__device__ float  g_hlast[BATCH * HID];                // final-step hidden in fp32
__device__ unsigned g_bar_count;                       // zero-init
__device__ unsigned g_bar_gen;                         // zero-init (monotonic across replays)

// ---------------- small PTX helpers ----------------
__device__ __forceinline__ void cp16(uint32_t dst, const void* src) {
    asm volatile("cp.async.cg.shared.global [%0], [%1], 16;\n" :: "r"(dst), "l"(src) : "memory");
}
__device__ __forceinline__ void cp_commit() {
    asm volatile("cp.async.commit_group;\n" ::: "memory");
}
template <int N>
__device__ __forceinline__ void cp_wait() {
    asm volatile("cp.async.wait_group %0;\n" :: "n"(N) : "memory");
}
__device__ __forceinline__ void ldsm_x4(uint32_t addr, uint32_t& r0, uint32_t& r1, uint32_t& r2, uint32_t& r3) {
    asm volatile("ldmatrix.sync.aligned.m8n8.x4.shared.b16 {%0,%1,%2,%3}, [%4];\n"
                 : "=r"(r0), "=r"(r1), "=r"(r2), "=r"(r3) : "r"(addr));
}
__device__ __forceinline__ void ldsm_x2(uint32_t addr, uint32_t& r0, uint32_t& r1) {
    asm volatile("ldmatrix.sync.aligned.m8n8.x2.shared.b16 {%0,%1}, [%2];\n"
                 : "=r"(r0), "=r"(r1) : "r"(addr));
}
__device__ __forceinline__ void mma16816(float* c, uint32_t a0, uint32_t a1, uint32_t a2, uint32_t a3,
                                         uint32_t b0, uint32_t b1) {
    asm volatile("mma.sync.aligned.m16n8k16.row.col.f32.f16.f16.f32 "
                 "{%0,%1,%2,%3},{%4,%5,%6,%7},{%8,%9},{%0,%1,%2,%3};\n"
                 : "+f"(c[0]), "+f"(c[1]), "+f"(c[2]), "+f"(c[3])
                 : "r"(a0), "r"(a1), "r"(a2), "r"(a3), "r"(b0), "r"(b1));
}

// ---------------- grid barrier (sense-reversal via generation counter) ----------------
// Safe across graph replays: count returns to 0 each barrier, gen only ever increments.
__device__ __forceinline__ void grid_barrier() {
    __syncthreads();
    if (threadIdx.x == 0) {
        unsigned my = *(volatile unsigned*)&g_bar_gen;  // read before arrive: release requires our arrival
        __threadfence();
        unsigned a = atomicAdd(&g_bar_count, 1u);
        if (a == NBLK - 1) {
            *(volatile unsigned*)&g_bar_count = 0u;
            __threadfence();
            atomicAdd(&g_bar_gen, 1u);
        } else {
            while (*(volatile unsigned*)&g_bar_gen == my) { __nanosleep(40); }
        }
        __threadfence();
    }
    __syncthreads();
}

// ---------------- kernel 1: transpose/pad x to fp16 [T][B][128] ----------------
__global__ void __launch_bounds__(256) xform_kernel(const float* __restrict__ x) {
    int t = blockIdx.x;
    const float* xs = x + (size_t)t * BATCH * DIM;
    __half* o = g_xT + (size_t)t * BATCH * XW;
    for (int i = threadIdx.x; i < BATCH * XW; i += 256) {
        int b = i >> 7, k = i & 127;
        float v = (k < DIM) ? xs[b * DIM + k] : 0.0f;
        o[i] = __float2half_rn(v);
    }
}

// ---------------- kernel 2: persistent RNN ----------------
__global__ void __launch_bounds__(NTH, 1)
rnn_kernel(const float* __restrict__ W_ih, const float* __restrict__ b_ih,
           const float* __restrict__ W_hh, const float* __restrict__ b_hh,
           const float* __restrict__ W_out, const float* __restrict__ b_out,
           float* __restrict__ out)
{
    extern __shared__ char smem[];
    __half* sW    = (__half*)(smem + SMEM_W_OFF);
    float*  sBias = (float*)(smem + SMEM_BIAS_OFF);

    const int tid = threadIdx.x;
    const int blk = blockIdx.x;
    const int j0  = blk * JT;

    // ---- prologue: zero W region (covers pads), then fill fp16 W slice ----
    for (int i = tid; i < (JT * WPITCH_B) / 4; i += NTH)
        ((uint32_t*)sW)[i] = 0u;
    __syncthreads();
    for (int i = tid; i < JT * HID; i += NTH) {
        int n = i >> 10, k = i & 1023;
        sW[n * WPITCH_H + k] = __float2half_rn(W_hh[(j0 + n) * HID + k]);
    }
    for (int i = tid; i < JT * DIM; i += NTH) {
        int n = i / DIM, d = i % DIM;
        sW[n * WPITCH_H + HID + d] = __float2half_rn(W_ih[(j0 + n) * DIM + d]);
    }
    if (tid < JT) sBias[tid] = b_ih[j0 + tid] + b_hh[j0 + tid];

    // zero h buffer 0 cooperatively: 128*1024 halfs = 16384 uint4, exactly grid*block threads
    {
        uint4 z = make_uint4(0u, 0u, 0u, 0u);
        int i = blk * NTH + tid;
        ((uint4*)g_h[0])[i] = z;
    }
    grid_barrier();

    // ---- warp/lane geometry ----
    const int lane = tid & 31;
    const int warp = tid >> 5;
    const int wm = warp & 3;        // 4 m-warps (32 rows each)
    const int wn = warp >> 2;       // 2 n-warps (8 cols each)
    const int m0 = wm * 32, n0 = wn * 8;

    uint32_t smem_u = (uint32_t)__cvta_generic_to_shared(smem);
    // A fragment ldmatrix.x4 base: lane L -> row m0+mt*16+(L%16), colgroup (L/16)*8 halfs
    uint32_t aoff0 = smem_u + (m0 + (lane & 15)) * APITCH_B + ((lane >> 4) * 16);
    uint32_t aoff1 = aoff0 + 16 * APITCH_B;
    // B fragment ldmatrix.x2 base: lanes 0-7 row n, lanes 8-15 row n col+8
    uint32_t boff = smem_u + SMEM_W_OFF + (n0 + (lane & 7)) * WPITCH_B + (((lane >> 3) & 1) * 16);

    const int er  = lane >> 2;          // epilogue row within m16
    const int ecc = (lane & 3) * 2;     // epilogue col pair within n8
    const int jc  = j0 + n0 + ecc;      // global output column

    // ---- time loop ----
    for (int t = 0; t < T_STEPS; ++t) {
        const __half* hcur = g_h[t & 1];
        __half* hnxt = g_h[(t + 1) & 1];
        const __half* hx = g_xT + (size_t)t * (BATCH * XW);

        float acc[8];
        #pragma unroll
        for (int i = 0; i < 8; ++i) acc[i] = 0.0f;

        // stage chunk 0 (h cols 0..127)
        {
            uint32_t sbase = smem_u;  // buf 0
            #pragma unroll
            for (int i = 0; i < 8; ++i) {
                int lin = tid + i * NTH;
                int row = lin >> 4, cc = lin & 15;
                cp16(sbase + row * APITCH_B + cc * 16, hcur + row * HID + cc * 8);
            }
            cp_commit();
        }

        #pragma unroll 1
        for (int c = 0; c < NCH; ++c) {
            if (c + 1 < NCH) {
                uint32_t sbase = smem_u + ((c + 1) & 1) * ABUF_B;
                const __half* src;
                int pitch;
                if (c + 1 < 8) { src = hcur + (c + 1) * KC; pitch = HID; }
                else           { src = hx;                  pitch = XW; }
                #pragma unroll
                for (int i = 0; i < 8; ++i) {
                    int lin = tid + i * NTH;
                    int row = lin >> 4, cc = lin & 15;
                    cp16(sbase + row * APITCH_B + cc * 16, src + row * pitch + cc * 8);
                }
                cp_commit();
                cp_wait<1>();
            } else {
                cp_wait<0>();
            }
            __syncthreads();

            uint32_t ab0 = aoff0 + (c & 1) * ABUF_B;
            uint32_t ab1 = aoff1 + (c & 1) * ABUF_B;
            uint32_t bb  = boff + c * 256;      // c*128 halfs
            #pragma unroll
            for (int s = 0; s < 8; ++s) {
                uint32_t b0, b1, a0, a1, a2, a3;
                ldsm_x2(bb + s * 32, b0, b1);
                ldsm_x4(ab0 + s * 32, a0, a1, a2, a3);
                mma16816(acc + 0, a0, a1, a2, a3, b0, b1);
                ldsm_x4(ab1 + s * 32, a0, a1, a2, a3);
                mma16816(acc + 4, a0, a1, a2, a3, b0, b1);
            }
            __syncthreads();
        }

        // ---- epilogue: bias + tanh + fp16 store ----
        float bia = sBias[n0 + ecc];
        float bib = sBias[n0 + ecc + 1];
        #pragma unroll
        for (int mt = 0; mt < 2; ++mt) {
            int row = m0 + mt * 16 + er;
            float h0 = tanhf(acc[mt * 4 + 0] + bia);
            float h1 = tanhf(acc[mt * 4 + 1] + bib);
            float h2 = tanhf(acc[mt * 4 + 2] + bia);
            float h3 = tanhf(acc[mt * 4 + 3] + bib);
            *reinterpret_cast<__half2*>(&hnxt[row * HID + jc])       = __floats2half2_rn(h0, h1);
            *reinterpret_cast<__half2*>(&hnxt[(row + 8) * HID + jc]) = __floats2half2_rn(h2, h3);
            if (t == T_STEPS - 1) {
                g_hlast[row * HID + jc]           = h0;
                g_hlast[row * HID + jc + 1]       = h1;
                g_hlast[(row + 8) * HID + jc]     = h2;
                g_hlast[(row + 8) * HID + jc + 1] = h3;
            }
        }
        grid_barrier();
    }

    // ---- final readout: out[b] = tanh(h_T . W_out + b_out), fp32 ----
    if (blk == 0) {
        for (int b = tid; b < BATCH; b += NTH) {
            float a = b_out[0];
            #pragma unroll 4
            for (int j = 0; j < HID; ++j)
                a += g_hlast[b * HID + j] * W_out[j];
            out[b] = tanhf(a);
        }
    }
}

// ---------------- launch ----------------
extern "C" void kernel_launch(void* const* d_in, const int* in_sizes, int n_in,
                              void* d_out, int out_size) {
    const float* x     = (const float*)d_in[0];
    const float* W_ih  = (const float*)d_in[1];
    const float* b_ih  = (const float*)d_in[2];
    const float* W_hh  = (const float*)d_in[3];
    const float* b_hh  = (const float*)d_in[4];
    const float* W_out = (const float*)d_in[5];
    const float* b_out = (const float*)d_in[6];

    cudaFuncSetAttribute(rnn_kernel, cudaFuncAttributeMaxDynamicSharedMemorySize, SMEM_TOTAL);

    xform_kernel<<<T_STEPS, 256>>>(x);
    rnn_kernel<<<NBLK, NTH, SMEM_TOTAL>>>(W_ih, b_ih, W_hh, b_hh, W_out, b_out, (float*)d_out);
}